// round 2
// baseline (speedup 1.0000x reference)
#include <cuda_runtime.h>
#include <cstdint>

// TraitSimilarity: out = (1/465) * sum over pairs 1<=j<k<32 of
//   [ (Gt[j,k] - cs_j*cs_k/N) >= 0 ] * (1 - Gp[j,k]/max(pn_j*pn_k, 1e-8))
// where Gp = y_pred^T y_pred, Gt = y_true^T y_true, cs = colsum(y_true),
// pn_j = sqrt(Gp[j,j]).

#define NBLK   1184   // 8 * 148 SMs -> 2 clean waves at occupancy 4
#define RPB    886    // ceil(2^20 / 1184)
#define TPB    128    // 4 warps
#define CHUNK  64     // rows per pipeline stage (64*128B = 8KB)
#define STAGES 3

// scratch: per block [Gp(1024) | Gt(1024) | colsum(32)] = 2080 floats
__device__ float g_scratch[NBLK * 2080];
__device__ float g_reduced[2080];

// ---------------- packed f32x2 helpers ----------------
__device__ __forceinline__ unsigned long long pack2(float lo, float hi) {
    unsigned long long r;
    asm("mov.b64 %0, {%1, %2};" : "=l"(r) : "f"(lo), "f"(hi));
    return r;
}
__device__ __forceinline__ void fma2(unsigned long long& d,
                                     unsigned long long a,
                                     unsigned long long b) {
    asm("fma.rn.f32x2 %0, %1, %2, %0;" : "+l"(d) : "l"(a), "l"(b));
}
__device__ __forceinline__ void add2(unsigned long long& d, unsigned long long a) {
    asm("add.rn.f32x2 %0, %0, %1;" : "+l"(d) : "l"(a));
}
__device__ __forceinline__ float2 unpack2(unsigned long long v) {
    float2 f;
    asm("mov.b64 {%0, %1}, %2;" : "=f"(f.x), "=f"(f.y) : "l"(v));
    return f;
}

// ---------------- cp.async helpers ----------------
__device__ __forceinline__ void cp16(uint32_t smem_dst, const void* gmem_src) {
    asm volatile("cp.async.cg.shared.global [%0], [%1], 16;\n"
                 :: "r"(smem_dst), "l"(gmem_src));
}
__device__ __forceinline__ void cp_commit() {
    asm volatile("cp.async.commit_group;\n" ::: "memory");
}
template <int W>
__device__ __forceinline__ void cp_wait() {
    asm volatile("cp.async.wait_group %0;\n" :: "n"(W) : "memory");
}

// ---------------- per-row FMA block ----------------
// Lane (jb in 0..7, kb in 0..3) accumulates C[4*jb+j][8*kb+kk], j in 0..3,
// kk in 0..7; acc[j*4+i] = f32x2 pair (kk=2i, kk=2i+1).
template <bool COLSUM>
__device__ __forceinline__ void row_fma(const float4* __restrict__ rowp,
                                        int jb, int kb,
                                        unsigned long long* __restrict__ acc,
                                        unsigned long long* __restrict__ cs) {
    float4 av = rowp[jb];
    const ulonglong2* rowq = (const ulonglong2*)rowp;
    ulonglong2 qa = rowq[2 * kb];
    ulonglong2 qb = rowq[2 * kb + 1];
    unsigned long long b0 = qa.x, b1 = qa.y, b2 = qb.x, b3 = qb.y;

    unsigned long long a0 = pack2(av.x, av.x);
    unsigned long long a1 = pack2(av.y, av.y);
    unsigned long long a2 = pack2(av.z, av.z);
    unsigned long long a3 = pack2(av.w, av.w);

    fma2(acc[0],  a0, b0); fma2(acc[1],  a0, b1); fma2(acc[2],  a0, b2); fma2(acc[3],  a0, b3);
    fma2(acc[4],  a1, b0); fma2(acc[5],  a1, b1); fma2(acc[6],  a1, b2); fma2(acc[7],  a1, b3);
    fma2(acc[8],  a2, b0); fma2(acc[9],  a2, b1); fma2(acc[10], a2, b2); fma2(acc[11], a2, b3);
    fma2(acc[12], a3, b0); fma2(acc[13], a3, b1); fma2(acc[14], a3, b2); fma2(acc[15], a3, b3);

    if (COLSUM) { add2(cs[0], b0); add2(cs[1], b1); add2(cs[2], b2); add2(cs[3], b3); }
}

// ---------------- pipelined Gram over one source matrix ----------------
template <bool COLSUM>
__device__ void gram_phase(const float* __restrict__ src, int row0, int nrows,
                           float* __restrict__ sbuf, int w, int jb, int kb,
                           unsigned long long* __restrict__ acc,
                           unsigned long long* __restrict__ cs) {
    const int tid = threadIdx.x;
    const int nchunks = (nrows + CHUNK - 1) / CHUNK;
    const uint32_t sb = (uint32_t)__cvta_generic_to_shared(sbuf);

    // prologue: stages 0 .. STAGES-2
#pragma unroll
    for (int c = 0; c < STAGES - 1; ++c) {
        if (c < nchunks) {
            const int cnt = min(CHUNK, nrows - c * CHUNK);
            const char* g = (const char*)(src + (size_t)(row0 + c * CHUNK) * 32);
            const int bytes = cnt * 128;
            for (int off = tid * 16; off < bytes; off += TPB * 16)
                cp16(sb + c * (CHUNK * 128) + off, g + off);
        }
        cp_commit();
    }

    for (int c = 0; c < nchunks; ++c) {
        cp_wait<STAGES - 2>();
        __syncthreads();

        const int cnt = min(CHUNK, nrows - c * CHUNK);
        const float4* bp = (const float4*)(sbuf + (c % STAGES) * (CHUNK * 32));
#pragma unroll 2
        for (int r = w; r < cnt; r += 4)
            row_fma<COLSUM>(bp + r * 8, jb, kb, acc, cs);

        __syncthreads();

        const int nc = c + STAGES - 1;
        if (nc < nchunks) {
            const int cnt2 = min(CHUNK, nrows - nc * CHUNK);
            const char* g = (const char*)(src + (size_t)(row0 + nc * CHUNK) * 32);
            const int bytes = cnt2 * 128;
            const uint32_t dst = sb + (nc % STAGES) * (CHUNK * 128);
            for (int off = tid * 16; off < bytes; off += TPB * 16)
                cp16(dst + off, g + off);
        }
        cp_commit();
    }
    cp_wait<0>();   // drain so buffers are reusable
    __syncthreads();
}

// cross-warp reduce of the 32x32 tile into scratch (reuses sbuf as smem)
__device__ void store_reduce(float* __restrict__ sbuf, float* __restrict__ outp,
                             int w, int jb, int kb,
                             const unsigned long long* __restrict__ acc) {
    float* sm = sbuf;  // 4 * 1024 floats
#pragma unroll
    for (int j = 0; j < 4; ++j) {
        const int jj = jb * 4 + j;
#pragma unroll
        for (int i = 0; i < 4; ++i) {
            float2 f = unpack2(acc[j * 4 + i]);
            const int kk = kb * 8 + 2 * i;
            sm[w * 1024 + jj * 32 + kk]     = f.x;
            sm[w * 1024 + jj * 32 + kk + 1] = f.y;
        }
    }
    __syncthreads();
    for (int o = threadIdx.x; o < 1024; o += TPB)
        outp[o] = sm[o] + sm[1024 + o] + sm[2048 + o] + sm[3072 + o];
    __syncthreads();
}

__global__ void __launch_bounds__(TPB, 4)
gram_kernel(const float* __restrict__ yp, const float* __restrict__ yt, int N) {
    __shared__ __align__(16) float sbuf[STAGES * CHUNK * 32];  // 24KB
    __shared__ float smcs[4][32];

    const int w    = threadIdx.x >> 5;
    const int lane = threadIdx.x & 31;
    const int jb   = lane >> 2;
    const int kb   = lane & 3;

    const int row0  = blockIdx.x * RPB;
    const int nrows = min(RPB, N - row0);
    float* outb = &g_scratch[(size_t)blockIdx.x * 2080];

    unsigned long long acc[16];
    unsigned long long cs[4];

    // ---------- phase 1: Gp from y_pred ----------
#pragma unroll
    for (int i = 0; i < 16; ++i) acc[i] = 0ull;
    gram_phase<false>(yp, row0, nrows, sbuf, w, jb, kb, acc, cs);
    store_reduce(sbuf, outb, w, jb, kb, acc);

    // ---------- phase 2: Gt + colsum from y_true ----------
#pragma unroll
    for (int i = 0; i < 16; ++i) acc[i] = 0ull;
#pragma unroll
    for (int i = 0; i < 4; ++i) cs[i] = 0ull;
    gram_phase<true>(yt, row0, nrows, sbuf, w, jb, kb, acc, cs);

    // colsum: lanes with jb==0 hold this warp's colsum for k = 8*kb..8*kb+7
    if (jb == 0) {
#pragma unroll
        for (int i = 0; i < 4; ++i) {
            float2 f = unpack2(cs[i]);
            smcs[w][kb * 8 + 2 * i]     = f.x;
            smcs[w][kb * 8 + 2 * i + 1] = f.y;
        }
    }
    store_reduce(sbuf, outb + 1024, w, jb, kb, acc);
    if (threadIdx.x < 32) {
        const int t = threadIdx.x;
        outb[2048 + t] = smcs[0][t] + smcs[1][t] + smcs[2][t] + smcs[3][t];
    }
}

// ---------------- cross-block reduction (deterministic order) ----------------
__global__ void reduce_kernel() {
    __shared__ float sm[256];
    const int ol = threadIdx.x & 15;
    const int b0 = threadIdx.x >> 4;
    const int o  = blockIdx.x * 16 + ol;

    float s = 0.0f;
    for (int b = b0; b < NBLK; b += 16)
        s += g_scratch[(size_t)b * 2080 + o];
    sm[threadIdx.x] = s;
    __syncthreads();
#pragma unroll
    for (int d = 8; d > 0; d >>= 1) {
        if (b0 < d) sm[b0 * 16 + ol] += sm[(b0 + d) * 16 + ol];
        __syncthreads();
    }
    if (threadIdx.x < 16)
        g_reduced[blockIdx.x * 16 + threadIdx.x] = sm[threadIdx.x];
}

// ---------------- finalize: one warp ----------------
__global__ void final_kernel(float* __restrict__ out, float invN) {
    __shared__ float pn[32], csm[32];
    const int lane = threadIdx.x;
    pn[lane]  = sqrtf(g_reduced[lane * 33]);       // sqrt(Gp[j][j])
    csm[lane] = g_reduced[2048 + lane];
    __syncwarp();

    float sum = 0.0f;
    for (int idx = lane; idx < 465; idx += 32) {   // pairs 1 <= j < k < 32
        int j = 1, rem = idx;
        while (rem >= 31 - j) { rem -= 31 - j; ++j; }
        const int k = j + 1 + rem;
        const float num  = g_reduced[1024 + j * 32 + k] - csm[j] * csm[k] * invN;
        const float cosv = g_reduced[j * 32 + k] / fmaxf(pn[j] * pn[k], 1e-8f);
        if (num >= 0.0f) sum += 1.0f - cosv;
    }
#pragma unroll
    for (int d = 16; d > 0; d >>= 1)
        sum += __shfl_down_sync(0xffffffffu, sum, d);
    if (lane == 0) out[0] = sum / 465.0f;
}

extern "C" void kernel_launch(void* const* d_in, const int* in_sizes, int n_in,
                              void* d_out, int out_size) {
    const float* yp = (const float*)d_in[0];   // y_pred [N, 32]
    const float* yt = (const float*)d_in[1];   // y_true [N, 32]
    const int N = in_sizes[0] / 32;

    gram_kernel<<<NBLK, TPB>>>(yp, yt, N);
    reduce_kernel<<<130, 256>>>();
    final_kernel<<<1, 32>>>((float*)d_out, 1.0f / (float)N);
}

// round 3
// speedup vs baseline: 1.2929x; 1.2929x over previous
#include <cuda_runtime.h>
#include <cstdint>

// TraitSimilarity: out = (1/465) * sum over pairs 1<=j<k<32 of
//   [ (Gt[j,k] - cs_j*cs_k/N) >= 0 ] * (1 - Gp[j,k]/max(pn_j*pn_k, 1e-8))
// Gp = y_pred^T y_pred, Gt = y_true^T y_true, cs = colsum(y_true), pn=sqrt(diag Gp)

#define NBLK 740     // 5 CTAs/SM * 148 SMs -> one clean wave
#define TPB  128     // 4 warps

// scratch: per block [Gp(1024) | Gt(1024) | colsum(32)] = 2080 floats
__device__ float g_scratch[NBLK * 2080];
__device__ float g_reduced[2080];

// ---------------- packed f32x2 helpers ----------------
__device__ __forceinline__ unsigned long long pack2(float lo, float hi) {
    unsigned long long r;
    asm("mov.b64 %0, {%1, %2};" : "=l"(r) : "f"(lo), "f"(hi));
    return r;
}
__device__ __forceinline__ void fma2(unsigned long long& d,
                                     unsigned long long a,
                                     unsigned long long b) {
    asm("fma.rn.f32x2 %0, %1, %2, %0;" : "+l"(d) : "l"(a), "l"(b));
}
__device__ __forceinline__ void add2(unsigned long long& d, unsigned long long a) {
    asm("add.rn.f32x2 %0, %0, %1;" : "+l"(d) : "l"(a));
}
__device__ __forceinline__ float2 unpack2(unsigned long long v) {
    float2 f;
    asm("mov.b64 {%0, %1}, %2;" : "=f"(f.x), "=f"(f.y) : "l"(v));
    return f;
}

// ---------------- per-row FMA block ----------------
// Lane (jb in 0..7, kb in 0..3) accumulates C[4*jb+j][8*kb+kk], j 0..3, kk 0..7;
// acc[j*4+i] = f32x2 pair (kk=2i, kk=2i+1).
template <bool COLSUM>
__device__ __forceinline__ void row_fma(float4 av, ulonglong2 qa, ulonglong2 qb,
                                        unsigned long long* __restrict__ acc,
                                        unsigned long long* __restrict__ cs) {
    unsigned long long b0 = qa.x, b1 = qa.y, b2 = qb.x, b3 = qb.y;
    unsigned long long a0 = pack2(av.x, av.x);
    unsigned long long a1 = pack2(av.y, av.y);
    unsigned long long a2 = pack2(av.z, av.z);
    unsigned long long a3 = pack2(av.w, av.w);

    fma2(acc[0],  a0, b0); fma2(acc[1],  a0, b1); fma2(acc[2],  a0, b2); fma2(acc[3],  a0, b3);
    fma2(acc[4],  a1, b0); fma2(acc[5],  a1, b1); fma2(acc[6],  a1, b2); fma2(acc[7],  a1, b3);
    fma2(acc[8],  a2, b0); fma2(acc[9],  a2, b1); fma2(acc[10], a2, b2); fma2(acc[11], a2, b3);
    fma2(acc[12], a3, b0); fma2(acc[13], a3, b1); fma2(acc[14], a3, b2); fma2(acc[15], a3, b3);

    if (COLSUM) { add2(cs[0], b0); add2(cs[1], b1); add2(cs[2], b2); add2(cs[3], b3); }
}

// ---------------- Gram over one source: batched loads (MLP=12) ----------------
template <bool COLSUM>
__device__ void gram_phase(const float* __restrict__ src, int row0, int rend,
                           int jb, int kb,
                           unsigned long long* __restrict__ acc,
                           unsigned long long* __restrict__ cs) {
    int r = row0;
    for (; r + 4 <= rend; r += 4) {
        float4 a[4]; ulonglong2 q0[4], q1[4];
#pragma unroll
        for (int u = 0; u < 4; ++u) {
            const float4* rowp = (const float4*)(src + (size_t)(r + u) * 32);
            a[u]  = rowp[jb];
            const ulonglong2* rowq = (const ulonglong2*)rowp;
            q0[u] = rowq[2 * kb];
            q1[u] = rowq[2 * kb + 1];
        }
#pragma unroll
        for (int u = 0; u < 4; ++u)
            row_fma<COLSUM>(a[u], q0[u], q1[u], acc, cs);
    }
    for (; r < rend; ++r) {
        const float4* rowp = (const float4*)(src + (size_t)r * 32);
        const ulonglong2* rowq = (const ulonglong2*)rowp;
        row_fma<COLSUM>(rowp[jb], rowq[2 * kb], rowq[2 * kb + 1], acc, cs);
    }
}

// cross-warp reduce of the 32x32 tile into scratch
__device__ void store_reduce(float (*sm)[1024], float* __restrict__ outp,
                             int w, int jb, int kb,
                             const unsigned long long* __restrict__ acc) {
#pragma unroll
    for (int j = 0; j < 4; ++j) {
        const int jj = jb * 4 + j;
#pragma unroll
        for (int i = 0; i < 4; ++i) {
            float2 f = unpack2(acc[j * 4 + i]);
            const int kk = kb * 8 + 2 * i;
            sm[w][jj * 32 + kk]     = f.x;
            sm[w][jj * 32 + kk + 1] = f.y;
        }
    }
    __syncthreads();
    for (int o = threadIdx.x; o < 1024; o += TPB)
        outp[o] = sm[0][o] + sm[1][o] + sm[2][o] + sm[3][o];
    __syncthreads();
}

__global__ void __launch_bounds__(TPB, 5)
gram_kernel(const float* __restrict__ yp, const float* __restrict__ yt, int N) {
    __shared__ float sm[4][1024];
    __shared__ float smcs[4][32];

    const int w    = threadIdx.x >> 5;
    const int lane = threadIdx.x & 31;
    const int jb   = lane >> 2;
    const int kb   = lane & 3;

    const int rpb   = (N + NBLK - 1) / NBLK;
    const int brow0 = blockIdx.x * rpb;
    const int nrows = min(rpb, N - brow0);
    const int rpw   = (nrows + 3) / 4;
    const int row0  = brow0 + w * rpw;
    const int rend  = min(brow0 + nrows, row0 + rpw);

    float* outb = &g_scratch[(size_t)blockIdx.x * 2080];

    unsigned long long acc[16];
    unsigned long long cs[4];

    // ---------- phase 1: Gp from y_pred ----------
#pragma unroll
    for (int i = 0; i < 16; ++i) acc[i] = 0ull;
    gram_phase<false>(yp, row0, rend, jb, kb, acc, cs);
    store_reduce(sm, outb, w, jb, kb, acc);

    // ---------- phase 2: Gt + colsum from y_true ----------
#pragma unroll
    for (int i = 0; i < 16; ++i) acc[i] = 0ull;
#pragma unroll
    for (int i = 0; i < 4; ++i) cs[i] = 0ull;
    gram_phase<true>(yt, row0, rend, jb, kb, acc, cs);

    if (jb == 0) {   // lane holds warp colsum for k = 8*kb .. 8*kb+7
#pragma unroll
        for (int i = 0; i < 4; ++i) {
            float2 f = unpack2(cs[i]);
            smcs[w][kb * 8 + 2 * i]     = f.x;
            smcs[w][kb * 8 + 2 * i + 1] = f.y;
        }
    }
    store_reduce(sm, outb + 1024, w, jb, kb, acc);
    if (threadIdx.x < 32) {
        const int t = threadIdx.x;
        outb[2048 + t] = smcs[0][t] + smcs[1][t] + smcs[2][t] + smcs[3][t];
    }
}

// ---------------- cross-block reduction (deterministic order) ----------------
__global__ void reduce_kernel() {
    __shared__ float sm[256];
    const int ol = threadIdx.x & 15;
    const int b0 = threadIdx.x >> 4;
    const int o  = blockIdx.x * 16 + ol;

    float s = 0.0f;
    for (int b = b0; b < NBLK; b += 16)
        s += g_scratch[(size_t)b * 2080 + o];
    sm[threadIdx.x] = s;
    __syncthreads();
#pragma unroll
    for (int d = 8; d > 0; d >>= 1) {
        if (b0 < d) sm[b0 * 16 + ol] += sm[(b0 + d) * 16 + ol];
        __syncthreads();
    }
    if (threadIdx.x < 16)
        g_reduced[blockIdx.x * 16 + threadIdx.x] = sm[threadIdx.x];
}

// ---------------- finalize: one warp ----------------
__global__ void final_kernel(float* __restrict__ out, float invN) {
    __shared__ float pn[32], csm[32];
    const int lane = threadIdx.x;
    pn[lane]  = sqrtf(g_reduced[lane * 33]);       // sqrt(Gp[j][j])
    csm[lane] = g_reduced[2048 + lane];
    __syncwarp();

    float sum = 0.0f;
    for (int idx = lane; idx < 465; idx += 32) {   // pairs 1 <= j < k < 32
        int j = 1, rem = idx;
        while (rem >= 31 - j) { rem -= 31 - j; ++j; }
        const int k = j + 1 + rem;
        const float num  = g_reduced[1024 + j * 32 + k] - csm[j] * csm[k] * invN;
        const float cosv = g_reduced[j * 32 + k] / fmaxf(pn[j] * pn[k], 1e-8f);
        if (num >= 0.0f) sum += 1.0f - cosv;
    }
#pragma unroll
    for (int d = 16; d > 0; d >>= 1)
        sum += __shfl_down_sync(0xffffffffu, sum, d);
    if (lane == 0) out[0] = sum / 465.0f;
}

extern "C" void kernel_launch(void* const* d_in, const int* in_sizes, int n_in,
                              void* d_out, int out_size) {
    const float* yp = (const float*)d_in[0];   // y_pred [N, 32]
    const float* yt = (const float*)d_in[1];   // y_true [N, 32]
    const int N = in_sizes[0] / 32;

    gram_kernel<<<NBLK, TPB>>>(yp, yt, N);
    reduce_kernel<<<130, 256>>>();
    final_kernel<<<1, 32>>>((float*)d_out, 1.0f / (float)N);
}